// round 7
// baseline (speedup 1.0000x reference)
#include <cuda_runtime.h>

// B=32, L=1024, D=64.
// Algebraic collapse (verified R1-R4, rel_err ~1.4e-7):
//   out[b,0,:] = sum_l x[b,l,:] / 1024 ;  out[b,1:,:] = 0.
//   W1,b1,W2,b2,timestamp are dead inputs.
//
// R5: two-stage reduction inside ONE kernel (fence+counter, deterministic).
//   bids [0,256):    reduction. block = (b, h, rq): batch b, 128B column half
//                    h, row-quarter rq (256 rows). 8 loads/thread, partial
//                    (8 float4) -> g_scratch. Last arriving block of the 4
//                    for (b,h) sums partials in fixed order, writes out row 0.
//   bids [256,1184): zeroing of out rows 1..1023 (disjoint from row-0 writes).

#define RED_BLOCKS   256
#define ZERO_BLOCKS  928
#define TOTAL_BLOCKS (RED_BLOCKS + ZERO_BLOCKS)
#define NTHREADS     256

#define F4_PER_BATCH 16384u   // 1024 rows * 16 float4
#define F4_PER_ROW   16u
#define N_F4_TOTAL   (32u * F4_PER_BATCH)

// scratch: (b,h,chunk,col) = 32*2*4*8 float4 ; counters per (b,h)
__device__ float4 g_scratch[32 * 2 * 4 * 8];
__device__ int    g_counters[64];   // zero-init at load; each replay returns to 0

__device__ __forceinline__ void f4add(float4& a, const float4& b) {
    a.x += b.x; a.y += b.y; a.z += b.z; a.w += b.w;
}

__device__ __forceinline__ float4 f4shfl_down(float4 v, int delta) {
    v.x = __shfl_down_sync(0xffffffffu, v.x, delta);
    v.y = __shfl_down_sync(0xffffffffu, v.y, delta);
    v.z = __shfl_down_sync(0xffffffffu, v.z, delta);
    v.w = __shfl_down_sync(0xffffffffu, v.w, delta);
    return v;
}

__global__ void __launch_bounds__(NTHREADS) um_fused_kernel(
    const float4* __restrict__ x4, float4* __restrict__ out4)
{
    const int bid = blockIdx.x;
    const int tid = threadIdx.x;

    if (bid < RED_BLOCKS) {
        // block = (b, h, rq): bid = ((b*2)+h)*4 + rq
        const int rq   = bid & 3;
        const int h    = (bid >> 2) & 1;
        const int b    = bid >> 3;
        const int slot = (b << 1) | h;           // 0..63

        const int c  = tid & 7;                  // float4 column in 128B slice
        const int lg = tid >> 3;                 // 0..31 row group

        const float4* base = x4 + (size_t)b * F4_PER_BATCH
                                + (size_t)(rq * 256) * F4_PER_ROW
                                + h * 8 + c;

        // 8 loads/thread, two independent batches of 4 (16 accum regs)
        float4 a0 = make_float4(0,0,0,0), a1 = a0, a2 = a0, a3 = a0;
        {
            float4 v0 = base[(size_t)(lg +   0) * F4_PER_ROW];
            float4 v1 = base[(size_t)(lg +  32) * F4_PER_ROW];
            float4 v2 = base[(size_t)(lg +  64) * F4_PER_ROW];
            float4 v3 = base[(size_t)(lg +  96) * F4_PER_ROW];
            f4add(a0, v0); f4add(a1, v1); f4add(a2, v2); f4add(a3, v3);
            v0 = base[(size_t)(lg + 128) * F4_PER_ROW];
            v1 = base[(size_t)(lg + 160) * F4_PER_ROW];
            v2 = base[(size_t)(lg + 192) * F4_PER_ROW];
            v3 = base[(size_t)(lg + 224) * F4_PER_ROW];
            f4add(a0, v0); f4add(a1, v1); f4add(a2, v2); f4add(a3, v3);
        }
        f4add(a0, a1); f4add(a2, a3); f4add(a0, a2);

        // warp reduce: lanes sharing (lane & 7) share a column
        f4add(a0, f4shfl_down(a0, 16));
        f4add(a0, f4shfl_down(a0, 8));

        __shared__ float4 sm[8][8];              // [warp][col]
        __shared__ int    s_old;
        const int lane = tid & 31;
        const int wid  = tid >> 5;
        if (lane < 8) sm[wid][lane] = a0;
        __syncthreads();

        if (tid < 8) {
            float4 t = sm[0][tid];
            #pragma unroll
            for (int w = 1; w < 8; ++w) f4add(t, sm[w][tid]);
            g_scratch[(slot * 4 + rq) * 8 + tid] = t;
            __threadfence();                     // publish partial (release)
        }
        __syncthreads();

        if (tid == 0) s_old = atomicAdd(&g_counters[slot], 1);
        __syncthreads();

        if (s_old == 3) {
            // last block for (b,h): sum 4 partials in fixed order
            if (tid < 8) {
                __threadfence();                 // acquire
                const float4* sc = &g_scratch[slot * 4 * 8];
                float4 t = sc[0 * 8 + tid];
                f4add(t, sc[1 * 8 + tid]);
                f4add(t, sc[2 * 8 + tid]);
                f4add(t, sc[3 * 8 + tid]);
                const float inv = 1.0f / 1024.0f;
                t.x *= inv; t.y *= inv; t.z *= inv; t.w *= inv;
                out4[(size_t)b * F4_PER_BATCH + h * 8 + tid] = t;
            }
            if (tid == 0) g_counters[slot] = 0;  // reset for next replay
        }
    } else {
        // ---- zeroing: everything except row 0 of each batch ---------------
        const unsigned zid  = (unsigned)(bid - RED_BLOCKS);
        const unsigned step = ZERO_BLOCKS * (unsigned)NTHREADS;
        const float4 z = make_float4(0.f, 0.f, 0.f, 0.f);
        for (unsigned i = zid * (unsigned)NTHREADS + (unsigned)tid;
             i < N_F4_TOTAL; i += step) {
            if ((i & (F4_PER_BATCH - 1u)) >= F4_PER_ROW)   // skip row 0
                out4[i] = z;
        }
    }
}

extern "C" void kernel_launch(void* const* d_in, const int* in_sizes, int n_in,
                              void* d_out, int out_size) {
    const float4* x4 = (const float4*)d_in[0];   // user_embedding [32,1024,64]
    float4* out4 = (float4*)d_out;               // [32,1024,64]
    um_fused_kernel<<<TOTAL_BLOCKS, NTHREADS>>>(x4, out4);
}

// round 8
// speedup vs baseline: 1.3478x; 1.3478x over previous
#include <cuda_runtime.h>

// B=32, L=1024, D=64.
// Algebraic collapse (verified R1-R5, rel_err ~1.4e-7):
//   out[b,0,:] = sum_l x[b,l,:] / 1024 ;  out[b,1:,:] = 0.
//   W1,b1,W2,b2,timestamp are dead inputs.
//
// R6: role-partitioned SMs. Grid = 148 x 1024 threads (1 CTA/SM).
//   bids [0,64):   READ blocks. Block = (batch b, 128B column half h),
//                  exclusive owner of out[b,0, h*32 : h*32+32). 1024 threads,
//                  8 fully-batched LDG.128/thread (explicit v[8] array, one
//                  base reg + immediate offsets), warp = 4 rows x 128B full
//                  lines. One smem barrier, no atomics, no fences.
//   bids [64,148): ZERO blocks. Grid-stride STG.128 of zeros over all of out
//                  except row 0 of each batch (disjoint from READ writes).

#define RED_BLOCKS   64
#define TOTAL_BLOCKS 148
#define ZERO_BLOCKS  (TOTAL_BLOCKS - RED_BLOCKS)
#define NTHREADS     1024

#define F4_PER_BATCH 16384u   // 1024 rows * 16 float4
#define F4_PER_ROW   16u
#define N_F4_TOTAL   (32u * F4_PER_BATCH)

__device__ __forceinline__ void f4add(float4& a, const float4& b) {
    a.x += b.x; a.y += b.y; a.z += b.z; a.w += b.w;
}

__device__ __forceinline__ float4 f4shfl_down(float4 v, int delta) {
    v.x = __shfl_down_sync(0xffffffffu, v.x, delta);
    v.y = __shfl_down_sync(0xffffffffu, v.y, delta);
    v.z = __shfl_down_sync(0xffffffffu, v.z, delta);
    v.w = __shfl_down_sync(0xffffffffu, v.w, delta);
    return v;
}

__global__ void __launch_bounds__(NTHREADS, 1) um_fused_kernel(
    const float4* __restrict__ x4, float4* __restrict__ out4)
{
    const int bid = blockIdx.x;
    const int tid = threadIdx.x;

    if (bid < RED_BLOCKS) {
        // ---- READ block: (b, h) owns the 128B slice h of row 0 -----------
        const int b  = bid >> 1;
        const int h  = bid & 1;
        const int c  = tid & 7;        // float4 column within 128B slice
        const int lg = tid >> 3;       // 0..127: row group

        const float4* base = x4 + (size_t)b * F4_PER_BATCH
                                + (size_t)lg * F4_PER_ROW + h * 8 + c;

        // 8 independent LDG.128 from one base + immediate offsets (MLP=8)
        float4 v[8];
        #pragma unroll
        for (int j = 0; j < 8; ++j)
            v[j] = base[(size_t)j * 128u * F4_PER_ROW];   // +128 rows each

        float4 a0 = v[0], a1 = v[1], a2 = v[2], a3 = v[3];
        f4add(a0, v[4]); f4add(a1, v[5]); f4add(a2, v[6]); f4add(a3, v[7]);
        f4add(a0, a1); f4add(a2, a3); f4add(a0, a2);

        // warp reduce: lanes sharing (lane & 7) share a column
        f4add(a0, f4shfl_down(a0, 16));
        f4add(a0, f4shfl_down(a0, 8));

        __shared__ float4 sm[32][8];   // [warp][col]
        const int lane = tid & 31;
        const int wid  = tid >> 5;
        if (lane < 8) sm[wid][lane] = a0;
        __syncthreads();

        if (tid < 8) {
            float4 t = sm[0][tid];
            #pragma unroll
            for (int w = 1; w < 32; ++w) f4add(t, sm[w][tid]);
            const float inv = 1.0f / 1024.0f;
            t.x *= inv; t.y *= inv; t.z *= inv; t.w *= inv;
            out4[(size_t)b * F4_PER_BATCH + h * 8 + tid] = t;
        }
    } else {
        // ---- ZERO block: everything except row 0 of each batch -----------
        const unsigned zid  = (unsigned)(bid - RED_BLOCKS);
        const unsigned step = ZERO_BLOCKS * (unsigned)NTHREADS;
        const float4 z = make_float4(0.f, 0.f, 0.f, 0.f);
        for (unsigned i = zid * (unsigned)NTHREADS + (unsigned)tid;
             i < N_F4_TOTAL; i += step) {
            if ((i & (F4_PER_BATCH - 1u)) >= F4_PER_ROW)   // skip row 0
                out4[i] = z;
        }
    }
}

extern "C" void kernel_launch(void* const* d_in, const int* in_sizes, int n_in,
                              void* d_out, int out_size) {
    const float4* x4 = (const float4*)d_in[0];   // user_embedding [32,1024,64]
    float4* out4 = (float4*)d_out;               // [32,1024,64]
    um_fused_kernel<<<TOTAL_BLOCKS, NTHREADS>>>(x4, out4);
}